// round 16
// baseline (speedup 1.0000x reference)
#include <cuda_runtime.h>
#include <cuda_fp16.h>
#include <cstdint>

#define Nn 8
#define Cc 16
#define Ll 1024
#define Dd 7
#define Hh 16
#define SZ 112
#define PAD 8

// Scratch: Q/K in [bh, l, 8] (tf32-domain; Q pre-scaled by log2(e)/32);
// V in [bh, l, 8] fp32 with pad dim = 1.0 (becomes softmax denom via MMA).
__device__ float g_Q[Nn * Hh * Ll * PAD];
__device__ float g_K[Nn * Hh * Ll * PAD];
__device__ float g_V[Nn * Hh * Ll * PAD];

__device__ __forceinline__ float tf32r(float x) {
    uint32_t u; asm("cvt.rna.tf32.f32 %0, %1;" : "=r"(u) : "f"(x));
    return __uint_as_float(u);
}
// Pack two fp32 into one f16x2 register (lo = a, hi = b).
__device__ __forceinline__ uint32_t f16x2(float a, float b) {
    uint32_t r;
    asm("cvt.rn.f16x2.f32 %0, %1, %2;" : "=r"(r) : "f"(b), "f"(a));
    return r;
}
// Packed fp16 2^x (one MUFU op for two values).
__device__ __forceinline__ uint32_t ex2h2(uint32_t x) {
    uint32_t y; asm("ex2.approx.f16x2 %0, %1;" : "=r"(y) : "r"(x)); return y;
}
// D += A(16x8) @ B(8x8), tf32 in, fp32 accum.
__device__ __forceinline__ void mma_tf32_k8(float& d0, float& d1, float& d2, float& d3,
                                            uint32_t a0, uint32_t a1, uint32_t a2, uint32_t a3,
                                            uint32_t b0, uint32_t b1) {
    asm volatile(
        "mma.sync.aligned.m16n8k8.row.col.f32.tf32.tf32.f32 "
        "{%0,%1,%2,%3}, {%4,%5,%6,%7}, {%8,%9}, {%0,%1,%2,%3};"
        : "+f"(d0), "+f"(d1), "+f"(d2), "+f"(d3)
        : "r"(a0), "r"(a1), "r"(a2), "r"(a3), "r"(b0), "r"(b1));
}
// D += A(16x16) @ B(16x8), fp16 in, fp32 accum.
__device__ __forceinline__ void mma_f16_k16(float& d0, float& d1, float& d2, float& d3,
                                            uint32_t a0, uint32_t a1, uint32_t a2, uint32_t a3,
                                            uint32_t b0, uint32_t b1) {
    asm volatile(
        "mma.sync.aligned.m16n8k16.row.col.f32.f16.f16.f32 "
        "{%0,%1,%2,%3}, {%4,%5,%6,%7}, {%8,%9}, {%0,%1,%2,%3};"
        : "+f"(d0), "+f"(d1), "+f"(d2), "+f"(d3)
        : "r"(a0), "r"(a1), "r"(a2), "r"(a3), "r"(b0), "r"(b1));
}

// ---------------------------------------------------------------------------
// Tensor-core projection v3b (R15, unchanged): q/k/v = xf @ W^T + b.
// ---------------------------------------------------------------------------
__global__ __launch_bounds__(256) void proj_kernel(
    const float* __restrict__ x,
    const float* __restrict__ Wq, const float* __restrict__ bq,
    const float* __restrict__ Wk, const float* __restrict__ bk,
    const float* __restrict__ Wv, const float* __restrict__ bv)
{
    extern __shared__ float sm[];
    float* Wt = sm;                     // [112][116] o-major: Wt[o*116+i]
    float* As = sm + 112 * 116;         // [64][116] (overlaid with Os below)
    float* Os = As;                     // [64][133] output tile (reuses As)
    float* bs = As + 64 * 133;          // [112]

    const int z = blockIdx.y;
    const float* W = (z == 0) ? Wq : ((z == 1) ? Wk : Wv);
    const float* b = (z == 0) ? bq : ((z == 1) ? bk : bv);
    float* dst     = (z == 0) ? g_Q : ((z == 1) ? g_K : g_V);
    const float scale = (z == 0) ? (1.4426950408889634f / 32.0f) : 1.0f;
    const float padv  = (z == 2) ? 1.0f : 0.0f;
    const bool  do_tf = (z != 2);

    const int tid = threadIdx.x;
    const int nb  = (blockIdx.x * 128) >> 10;   // batch (constant per CTA)

    // Stage W o-major, tf32-rounded (conflict-free STS, coalesced LDG).
    for (int e = tid; e < SZ * SZ; e += 256) {
        int o = e / SZ, i = e - o * SZ;
        Wt[o * 116 + i] = tf32r(W[e]);
    }
    if (tid < SZ) bs[tid] = b[tid];

    const int wid = tid >> 5, lid = tid & 31;
    const int g = lid >> 2, t = lid & 3;
    const int rt = wid & 3;            // 16-row tile within 64 rows
    const int cw = wid >> 2;           // column half: cols cw*56

    for (int sub = 0; sub < 2; ++sub) {
        const int row0 = blockIdx.x * 128 + sub * 64;
        __syncthreads();   // W/bias ready (sub 0); As region reusable (sub 1)

        // Stage xf tile, tf32-rounded.
        for (int e = tid; e < 64 * SZ; e += 256) {
            int r = e / SZ, i = e - r * SZ;
            int l = (row0 + r) & 1023;
            int c = i / Dd, dd = i - c * Dd;
            As[r * 116 + i] = tf32r(x[(((nb * Cc + c) << 10) + l) * Dd + dd]);
        }
        __syncthreads();

        const float* A0 = As + (rt * 16 + g) * 116;
        const float* A1 = A0 + 8 * 116;

        // C-frags init with bias.
        float acc[7][4];
#pragma unroll
        for (int nt = 0; nt < 7; ++nt) {
            int n0 = cw * 56 + nt * 8;
            float b0 = bs[n0 + 2 * t], b1 = bs[n0 + 2 * t + 1];
            acc[nt][0] = b0; acc[nt][1] = b1;
            acc[nt][2] = b0; acc[nt][3] = b1;
        }

#pragma unroll
        for (int ks = 0; ks < 14; ++ks) {
            const int k0 = ks * 8;
            uint32_t a0 = __float_as_uint(A0[k0 + t]);
            uint32_t a1 = __float_as_uint(A1[k0 + t]);
            uint32_t a2 = __float_as_uint(A0[k0 + t + 4]);
            uint32_t a3 = __float_as_uint(A1[k0 + t + 4]);
            const float* B0 = Wt + (cw * 56 + g) * 116 + k0;   // o-major
#pragma unroll
            for (int nt = 0; nt < 7; ++nt) {
                uint32_t b0 = __float_as_uint(B0[nt * 8 * 116 + t]);
                uint32_t b1 = __float_as_uint(B0[nt * 8 * 116 + t + 4]);
                mma_tf32_k8(acc[nt][0], acc[nt][1], acc[nt][2], acc[nt][3],
                            a0, a1, a2, a3, b0, b1);
            }
        }
        __syncthreads();   // done reading As; Os may overwrite it

        // Stage outputs to SMEM: column o = cw*56 + nt*8 + 2t + j (0..111).
        const int rA = rt * 16 + g, rB = rA + 8;
#pragma unroll
        for (int nt = 0; nt < 7; ++nt) {
            int o0 = cw * 56 + nt * 8 + 2 * t;
#pragma unroll
            for (int j = 0; j < 2; ++j) {
                float vA = acc[nt][j]     * scale;
                float vB = acc[nt][2 + j] * scale;
                if (do_tf) { vA = tf32r(vA); vB = tf32r(vB); }
                Os[rA * 133 + o0 + j] = vA;
                Os[rB * 133 + o0 + j] = vB;
            }
        }
        __syncthreads();

        // Coalesced GMEM stores: warp spans 32 consecutive rows of one head.
        for (int e = tid; e < 1024; e += 256) {
            int head = e >> 6, r = e & 63;
            const float* os = Os + r * 133 + head * 7;
            int l = (row0 + r) & 1023;
            float4* p = (float4*)(dst + (((nb * Hh + head) << 10) + l) * PAD);
            p[0] = make_float4(os[0], os[1], os[2], os[3]);
            p[1] = make_float4(os[4], os[5], os[6], padv);
        }
    }
}

// ---------------------------------------------------------------------------
// Warp-MMA attention v2: paired-operand SMEM layouts. Per 16-key step:
// 2 LDS.64 (K pairs) + 1 LDS.64 (V pairs) + 2 tf32 QK MMAs + 4 f16x2 packs
// + 4 ex2.f16x2 + 1 fp16 AV MMA. All in-loop LDS banks = 8g+2t: the 16
// lanes of each LDS.64 phase hit 16 distinct banks (conflict-free).
// SMEM: KP [1024][4] float2 (32768 B) + Vq [64][8][4] uint2 (16384 B).
// ---------------------------------------------------------------------------
__global__ __launch_bounds__(256) void attn_kernel(float* __restrict__ out)
{
    extern __shared__ char smem[];
    float2* KP = (float2*)smem;               // KP[key*4+t] = (K[key][t], K[key][t+4])
    uint2*  Vq = (uint2*)(smem + 32768);      // Vq[c*32+g*4+t] = (vb0, vb1)

    const int tid = threadIdx.x;
    const int wid = tid >> 5, lid = tid & 31;
    const int g = lid >> 2, t = lid & 3;
    const int qt = blockIdx.x;
    const int bh = blockIdx.y;

    // Stage K pairs (coalesced scalar LDG, conflict-free STS.64).
    const float* gK = g_K + bh * Ll * PAD;
    for (int e = tid; e < 4096; e += 256) {
        int key = e >> 2, tt = e & 3;
        KP[e] = make_float2(gK[key * 8 + tt], gK[key * 8 + tt + 4]);
    }
    // Stage V pairs: thread (c, tt) builds Vq[c*32 + g*4 + tt] for g=0..7.
    {
        int c = tid >> 2, tt = tid & 3;
        const float4* gV4 = (const float4*)(g_V + bh * Ll * PAD);
        int k2a = c * 8 + tt, k2b = k2a + 4;
        float4 a0 = gV4[k2a * 4 + 0], a1 = gV4[k2a * 4 + 1];   // V[2k2a][0..7]
        float4 b0 = gV4[k2a * 4 + 2], b1 = gV4[k2a * 4 + 3];   // V[2k2a+1][0..7]
        float4 c0 = gV4[k2b * 4 + 0], c1 = gV4[k2b * 4 + 1];   // V[2k2b][0..7]
        float4 d0 = gV4[k2b * 4 + 2], d1 = gV4[k2b * 4 + 3];   // V[2k2b+1][0..7]
        uint2* dstp = Vq + c * 32 + tt;
        dstp[0]  = make_uint2(f16x2(a0.x, b0.x), f16x2(c0.x, d0.x));  // g=0
        dstp[4]  = make_uint2(f16x2(a0.y, b0.y), f16x2(c0.y, d0.y));
        dstp[8]  = make_uint2(f16x2(a0.z, b0.z), f16x2(c0.z, d0.z));
        dstp[12] = make_uint2(f16x2(a0.w, b0.w), f16x2(c0.w, d0.w));
        dstp[16] = make_uint2(f16x2(a1.x, b1.x), f16x2(c1.x, d1.x));
        dstp[20] = make_uint2(f16x2(a1.y, b1.y), f16x2(c1.y, d1.y));
        dstp[24] = make_uint2(f16x2(a1.z, b1.z), f16x2(c1.z, d1.z));
        dstp[28] = make_uint2(f16x2(a1.w, b1.w), f16x2(c1.w, d1.w));
    }

    // Q A-fragment (rows wid*16 + {g, g+8}, k-dims {t, t+4}).
    const float* qb = g_Q + (bh * Ll + qt * 128 + wid * 16) * PAD;
    const uint32_t qa0 = __float_as_uint(qb[g * 8 + t]);
    const uint32_t qa1 = __float_as_uint(qb[(g + 8) * 8 + t]);
    const uint32_t qa2 = __float_as_uint(qb[g * 8 + t + 4]);
    const uint32_t qa3 = __float_as_uint(qb[(g + 8) * 8 + t + 4]);
    __syncthreads();

    float o0 = 0.f, o1 = 0.f, o2 = 0.f, o3 = 0.f;   // out frag (cols=dims, col7=denom)

    const float2* Kb = KP + 4 * g + t;       // lane base; step stride 64
    const uint2*  Vb = Vq + 4 * g + t;       // lane base; step stride 32

#pragma unroll 4
    for (int c = 0; c < 64; ++c) {
        // --- QK: two 8-key tf32 MMAs; each B-frag is ONE LDS.64 ---
        float2 kA = Kb[64 * c];              // keys 16c+g:   (dim t, dim t+4)
        float2 kB = Kb[64 * c + 32];         // keys 16c+8+g
        float sa0 = 0.f, sa1 = 0.f, sa2 = 0.f, sa3 = 0.f;
        float sb0 = 0.f, sb1 = 0.f, sb2 = 0.f, sb3 = 0.f;
        mma_tf32_k8(sa0, sa1, sa2, sa3, qa0, qa1, qa2, qa3,
                    __float_as_uint(kA.x), __float_as_uint(kA.y));
        mma_tf32_k8(sb0, sb1, sb2, sb3, qa0, qa1, qa2, qa3,
                    __float_as_uint(kB.x), __float_as_uint(kB.y));

        // --- pack scores to f16x2, one packed MUFU exp per pair ---
        uint32_t wa0 = ex2h2(f16x2(sa0, sa1));
        uint32_t wa1 = ex2h2(f16x2(sa2, sa3));
        uint32_t wa2 = ex2h2(f16x2(sb0, sb1));
        uint32_t wa3 = ex2h2(f16x2(sb2, sb3));

        // --- AV: one k16 fp16 MMA; B-frag is ONE LDS.64 ---
        uint2 v = Vb[32 * c];
        mma_f16_k16(o0, o1, o2, o3, wa0, wa1, wa2, wa3, v.x, v.y);
    }

    // Denominator = col 7, held by lane (g,3) in o1 (row g) / o3 (row g+8).
    float sum0 = __shfl_sync(0xffffffffu, o1, (lid & ~3) | 3);
    float sum1 = __shfl_sync(0xffffffffu, o3, (lid & ~3) | 3);
    float i0 = 1.0f / sum0, i1 = 1.0f / sum1;

    const int row = bh * Ll + qt * 128 + wid * 16 + g;
    float* p0 = out + row * Dd;
    float* p1 = out + (row + 8) * Dd;
    p0[2 * t] = o0 * i0;
    p1[2 * t] = o2 * i1;
    if (t < 3) {
        p0[2 * t + 1] = o1 * i0;
        p1[2 * t + 1] = o3 * i1;
    }
}

extern "C" void kernel_launch(void* const* d_in, const int* in_sizes, int n_in,
                              void* d_out, int out_size)
{
    const float* x  = (const float*)d_in[0];
    const float* Wq = (const float*)d_in[1];
    const float* bq = (const float*)d_in[2];
    const float* Wk = (const float*)d_in[3];
    const float* bk = (const float*)d_in[4];
    const float* Wv = (const float*)d_in[5];
    const float* bv = (const float*)d_in[6];

    // SMEM: proj 112*116*4 + 64*133*4 + 448 = 86464 B; attn 49152 B.
    cudaFuncSetAttribute(proj_kernel, cudaFuncAttributeMaxDynamicSharedMemorySize, 86464);
    cudaFuncSetAttribute(attn_kernel, cudaFuncAttributeMaxDynamicSharedMemorySize, 49152);

    proj_kernel<<<dim3(64, 3, 1), 256, 86464>>>(x, Wq, bq, Wk, bk, Wv, bv);
    attn_kernel<<<dim3(8, 128, 1), 256, 49152>>>((float*)d_out);
}

// round 17
// speedup vs baseline: 1.0541x; 1.0541x over previous
#include <cuda_runtime.h>
#include <cuda_fp16.h>
#include <cstdint>

#define Nn 8
#define Cc 16
#define Ll 1024
#define Dd 7
#define Hh 16
#define SZ 112
#define PAD 8

// Scratch: Q/K in [bh, l, 8] (tf32-domain; Q pre-scaled by log2(e)/32);
// V in [bh, l, 8] fp32 with pad dim = 1.0 (becomes softmax denom via MMA).
__device__ float g_Q[Nn * Hh * Ll * PAD];
__device__ float g_K[Nn * Hh * Ll * PAD];
__device__ float g_V[Nn * Hh * Ll * PAD];

__device__ __forceinline__ float tf32r(float x) {
    uint32_t u; asm("cvt.rna.tf32.f32 %0, %1;" : "=r"(u) : "f"(x));
    return __uint_as_float(u);
}
// Pack two fp32 into one f16x2 register (lo = a, hi = b).
__device__ __forceinline__ uint32_t f16x2(float a, float b) {
    uint32_t r;
    asm("cvt.rn.f16x2.f32 %0, %1, %2;" : "=r"(r) : "f"(b), "f"(a));
    return r;
}
// Packed fp16 2^x (one MUFU op for two values).
__device__ __forceinline__ uint32_t ex2h2(uint32_t x) {
    uint32_t y; asm("ex2.approx.f16x2 %0, %1;" : "=r"(y) : "r"(x)); return y;
}
// D += A(16x8) @ B(8x8), tf32 in, fp32 accum.
__device__ __forceinline__ void mma_tf32_k8(float& d0, float& d1, float& d2, float& d3,
                                            uint32_t a0, uint32_t a1, uint32_t a2, uint32_t a3,
                                            uint32_t b0, uint32_t b1) {
    asm volatile(
        "mma.sync.aligned.m16n8k8.row.col.f32.tf32.tf32.f32 "
        "{%0,%1,%2,%3}, {%4,%5,%6,%7}, {%8,%9}, {%0,%1,%2,%3};"
        : "+f"(d0), "+f"(d1), "+f"(d2), "+f"(d3)
        : "r"(a0), "r"(a1), "r"(a2), "r"(a3), "r"(b0), "r"(b1));
}
// D += A(16x16) @ B(16x8), fp16 in, fp32 accum.
__device__ __forceinline__ void mma_f16_k16(float& d0, float& d1, float& d2, float& d3,
                                            uint32_t a0, uint32_t a1, uint32_t a2, uint32_t a3,
                                            uint32_t b0, uint32_t b1) {
    asm volatile(
        "mma.sync.aligned.m16n8k16.row.col.f32.f16.f16.f32 "
        "{%0,%1,%2,%3}, {%4,%5,%6,%7}, {%8,%9}, {%0,%1,%2,%3};"
        : "+f"(d0), "+f"(d1), "+f"(d2), "+f"(d3)
        : "r"(a0), "r"(a1), "r"(a2), "r"(a3), "r"(b0), "r"(b1));
}

// ---------------------------------------------------------------------------
// Tensor-core projection v3b (R15, unchanged): q/k/v = xf @ W^T + b.
// ---------------------------------------------------------------------------
__global__ __launch_bounds__(256) void proj_kernel(
    const float* __restrict__ x,
    const float* __restrict__ Wq, const float* __restrict__ bq,
    const float* __restrict__ Wk, const float* __restrict__ bk,
    const float* __restrict__ Wv, const float* __restrict__ bv)
{
    extern __shared__ float sm[];
    float* Wt = sm;                     // [112][116] o-major: Wt[o*116+i]
    float* As = sm + 112 * 116;         // [64][116] (overlaid with Os below)
    float* Os = As;                     // [64][133] output tile (reuses As)
    float* bs = As + 64 * 133;          // [112]

    const int z = blockIdx.y;
    const float* W = (z == 0) ? Wq : ((z == 1) ? Wk : Wv);
    const float* b = (z == 0) ? bq : ((z == 1) ? bk : bv);
    float* dst     = (z == 0) ? g_Q : ((z == 1) ? g_K : g_V);
    const float scale = (z == 0) ? (1.4426950408889634f / 32.0f) : 1.0f;
    const float padv  = (z == 2) ? 1.0f : 0.0f;
    const bool  do_tf = (z != 2);

    const int tid = threadIdx.x;
    const int nb  = (blockIdx.x * 128) >> 10;   // batch (constant per CTA)

    // Stage W o-major, tf32-rounded (conflict-free STS, coalesced LDG).
    for (int e = tid; e < SZ * SZ; e += 256) {
        int o = e / SZ, i = e - o * SZ;
        Wt[o * 116 + i] = tf32r(W[e]);
    }
    if (tid < SZ) bs[tid] = b[tid];

    const int wid = tid >> 5, lid = tid & 31;
    const int g = lid >> 2, t = lid & 3;
    const int rt = wid & 3;            // 16-row tile within 64 rows
    const int cw = wid >> 2;           // column half: cols cw*56

    for (int sub = 0; sub < 2; ++sub) {
        const int row0 = blockIdx.x * 128 + sub * 64;
        __syncthreads();   // W/bias ready (sub 0); As region reusable (sub 1)

        // Stage xf tile, tf32-rounded.
        for (int e = tid; e < 64 * SZ; e += 256) {
            int r = e / SZ, i = e - r * SZ;
            int l = (row0 + r) & 1023;
            int c = i / Dd, dd = i - c * Dd;
            As[r * 116 + i] = tf32r(x[(((nb * Cc + c) << 10) + l) * Dd + dd]);
        }
        __syncthreads();

        const float* A0 = As + (rt * 16 + g) * 116;
        const float* A1 = A0 + 8 * 116;

        // C-frags init with bias.
        float acc[7][4];
#pragma unroll
        for (int nt = 0; nt < 7; ++nt) {
            int n0 = cw * 56 + nt * 8;
            float b0 = bs[n0 + 2 * t], b1 = bs[n0 + 2 * t + 1];
            acc[nt][0] = b0; acc[nt][1] = b1;
            acc[nt][2] = b0; acc[nt][3] = b1;
        }

#pragma unroll
        for (int ks = 0; ks < 14; ++ks) {
            const int k0 = ks * 8;
            uint32_t a0 = __float_as_uint(A0[k0 + t]);
            uint32_t a1 = __float_as_uint(A1[k0 + t]);
            uint32_t a2 = __float_as_uint(A0[k0 + t + 4]);
            uint32_t a3 = __float_as_uint(A1[k0 + t + 4]);
            const float* B0 = Wt + (cw * 56 + g) * 116 + k0;   // o-major
#pragma unroll
            for (int nt = 0; nt < 7; ++nt) {
                uint32_t b0 = __float_as_uint(B0[nt * 8 * 116 + t]);
                uint32_t b1 = __float_as_uint(B0[nt * 8 * 116 + t + 4]);
                mma_tf32_k8(acc[nt][0], acc[nt][1], acc[nt][2], acc[nt][3],
                            a0, a1, a2, a3, b0, b1);
            }
        }
        __syncthreads();   // done reading As; Os may overwrite it

        // Stage outputs to SMEM: column o = cw*56 + nt*8 + 2t + j (0..111).
        const int rA = rt * 16 + g, rB = rA + 8;
#pragma unroll
        for (int nt = 0; nt < 7; ++nt) {
            int o0 = cw * 56 + nt * 8 + 2 * t;
#pragma unroll
            for (int j = 0; j < 2; ++j) {
                float vA = acc[nt][j]     * scale;
                float vB = acc[nt][2 + j] * scale;
                if (do_tf) { vA = tf32r(vA); vB = tf32r(vB); }
                Os[rA * 133 + o0 + j] = vA;
                Os[rB * 133 + o0 + j] = vB;
            }
        }
        __syncthreads();

        // Coalesced GMEM stores: warp spans 32 consecutive rows of one head.
        for (int e = tid; e < 1024; e += 256) {
            int head = e >> 6, r = e & 63;
            const float* os = Os + r * 133 + head * 7;
            int l = (row0 + r) & 1023;
            float4* p = (float4*)(dst + (((nb * Hh + head) << 10) + l) * PAD);
            p[0] = make_float4(os[0], os[1], os[2], os[3]);
            p[1] = make_float4(os[4], os[5], os[6], padv);
        }
    }
}

// ---------------------------------------------------------------------------
// Warp-MMA attention v3: R11 layout (proven 31.8us) + split AV accumulators.
// The 64 AV MMAs previously formed one dependent HMMA chain (latency-bound,
// issue 41%). Two accumulator sets (even/odd step) double the chain ILP;
// merged with 4 FADDs at the end. Everything else identical to R11.
// SMEM: KT fp32 [8][1032] (33024 B) + Vp half2 [512][8] (16384 B) = 49408 B.
// ---------------------------------------------------------------------------
__global__ __launch_bounds__(256) void attn_kernel(float* __restrict__ out)
{
    extern __shared__ char smem[];
    float*   KT = (float*)smem;               // [8][1032]
    __half2* Vp = (__half2*)(smem + 33024);   // [512][8]: (V[2k],V[2k+1])[dim]

    const int tid = threadIdx.x;
    const int wid = tid >> 5, lid = tid & 31;
    const int g = lid >> 2, t = lid & 3;
    const int qt = blockIdx.x;
    const int bh = blockIdx.y;

    // Stage K^T.
    const float* gK = g_K + bh * Ll * PAD;
    for (int e = tid; e < 8192; e += 256) {
        int key = e >> 3, dim = e & 7;
        KT[dim * 1032 + key] = gK[e];
    }
    // Stage V packed: Vp[k2][dim] = half2(V[2k2][dim], V[2k2+1][dim]).
    {
        const float4* gV4 = (const float4*)(g_V + bh * Ll * PAD);
        for (int k2 = tid; k2 < 512; k2 += 256) {
            float4 e0a = gV4[k2 * 4 + 0], e0b = gV4[k2 * 4 + 1];
            float4 e1a = gV4[k2 * 4 + 2], e1b = gV4[k2 * 4 + 3];
            uint32_t* d = (uint32_t*)(Vp + k2 * 8);
            d[0] = f16x2(e0a.x, e1a.x);
            d[1] = f16x2(e0a.y, e1a.y);
            d[2] = f16x2(e0a.z, e1a.z);
            d[3] = f16x2(e0a.w, e1a.w);
            d[4] = f16x2(e0b.x, e1b.x);
            d[5] = f16x2(e0b.y, e1b.y);
            d[6] = f16x2(e0b.z, e1b.z);
            d[7] = f16x2(e0b.w, e1b.w);
        }
    }

    // Q A-fragment (rows wid*16 + {g, g+8}, k-dims {t, t+4}).
    const float* qb = g_Q + (bh * Ll + qt * 128 + wid * 16) * PAD;
    const uint32_t qa0 = __float_as_uint(qb[g * 8 + t]);
    const uint32_t qa1 = __float_as_uint(qb[(g + 8) * 8 + t]);
    const uint32_t qa2 = __float_as_uint(qb[g * 8 + t + 4]);
    const uint32_t qa3 = __float_as_uint(qb[(g + 8) * 8 + t + 4]);
    __syncthreads();

    // Two independent accumulator sets (even/odd step) -> 2x AV-chain ILP.
    float e0_ = 0.f, e1_ = 0.f, e2_ = 0.f, e3_ = 0.f;
    float p0_ = 0.f, p1_ = 0.f, p2_ = 0.f, p3_ = 0.f;

    const uint32_t* Vpu = (const uint32_t*)Vp;
    const float* KTt0 = KT + t * 1032;
    const float* KTt4 = KT + (t + 4) * 1032;

#pragma unroll 2
    for (int cc = 0; cc < 32; ++cc) {
#pragma unroll
        for (int h = 0; h < 2; ++h) {
            const int c = cc * 2 + h;
            const int k0 = c * 16;
            uint32_t ka0 = __float_as_uint(KTt0[k0 + g]);
            uint32_t ka1 = __float_as_uint(KTt4[k0 + g]);
            uint32_t kb0 = __float_as_uint(KTt0[k0 + 8 + g]);
            uint32_t kb1 = __float_as_uint(KTt4[k0 + 8 + g]);
            float sa0 = 0.f, sa1 = 0.f, sa2 = 0.f, sa3 = 0.f;
            float sb0 = 0.f, sb1 = 0.f, sb2 = 0.f, sb3 = 0.f;
            mma_tf32_k8(sa0, sa1, sa2, sa3, qa0, qa1, qa2, qa3, ka0, ka1);
            mma_tf32_k8(sb0, sb1, sb2, sb3, qa0, qa1, qa2, qa3, kb0, kb1);

            uint32_t wa0 = ex2h2(f16x2(sa0, sa1));
            uint32_t wa1 = ex2h2(f16x2(sa2, sa3));
            uint32_t wa2 = ex2h2(f16x2(sb0, sb1));
            uint32_t wa3 = ex2h2(f16x2(sb2, sb3));

            uint32_t vb0 = Vpu[(c * 8 + t) * 8 + g];
            uint32_t vb1 = Vpu[(c * 8 + t + 4) * 8 + g];
            if (h == 0)
                mma_f16_k16(e0_, e1_, e2_, e3_, wa0, wa1, wa2, wa3, vb0, vb1);
            else
                mma_f16_k16(p0_, p1_, p2_, p3_, wa0, wa1, wa2, wa3, vb0, vb1);
        }
    }

    float o0 = e0_ + p0_, o1 = e1_ + p1_, o2 = e2_ + p2_, o3 = e3_ + p3_;

    // Denominator = col 7, held by lane (g,3) in o1 (row g) / o3 (row g+8).
    float sum0 = __shfl_sync(0xffffffffu, o1, (lid & ~3) | 3);
    float sum1 = __shfl_sync(0xffffffffu, o3, (lid & ~3) | 3);
    float i0 = 1.0f / sum0, i1 = 1.0f / sum1;

    const int row = bh * Ll + qt * 128 + wid * 16 + g;
    float* p0 = out + row * Dd;
    float* p1 = out + (row + 8) * Dd;
    p0[2 * t] = o0 * i0;
    p1[2 * t] = o2 * i1;
    if (t < 3) {
        p0[2 * t + 1] = o1 * i0;
        p1[2 * t + 1] = o3 * i1;
    }
}

extern "C" void kernel_launch(void* const* d_in, const int* in_sizes, int n_in,
                              void* d_out, int out_size)
{
    const float* x  = (const float*)d_in[0];
    const float* Wq = (const float*)d_in[1];
    const float* bq = (const float*)d_in[2];
    const float* Wk = (const float*)d_in[3];
    const float* bk = (const float*)d_in[4];
    const float* Wv = (const float*)d_in[5];
    const float* bv = (const float*)d_in[6];

    // SMEM: proj 112*116*4 + 64*133*4 + 448 = 86464 B; attn 49408 B.
    cudaFuncSetAttribute(proj_kernel, cudaFuncAttributeMaxDynamicSharedMemorySize, 86464);
    cudaFuncSetAttribute(attn_kernel, cudaFuncAttributeMaxDynamicSharedMemorySize, 49408);

    proj_kernel<<<dim3(64, 3, 1), 256, 86464>>>(x, Wq, bq, Wk, bk, Wv, bv);
    attn_kernel<<<dim3(8, 128, 1), 256, 49408>>>((float*)d_out);
}